// round 15
// baseline (speedup 1.0000x reference)
#include <cuda_runtime.h>
#include <cuda_fp16.h>
#include <math.h>
#include <stdint.h>

// Problem dims (fixed by reference)
#define BB 4
#define TT 2048
#define EE 1024
#define HH 16
#define DD 64

// fp16 operand buffers use pair-sigma interleaved k-groups of 16:
//   pair j (elements 2j,2j+1) of a 16-group stored at pair-position
//   sigma(j) = ((j&3)<<1) | (j>>2).
// Then an m16n8k16 fragment's k-slots for thread cg are 4 contiguous fp16
// at offset 4*cg: pairs cg (k=2cg,2cg+1) and cg+4 (k=2cg+8,2cg+9).

__device__ __half g_qkv[(size_t)BB * TT * 3 * EE];  // Q/K pair-sigma'd d, Q pre-scaled
__device__ __half g_vt[(size_t)BB * HH * DD * TT];  // V^T: [b][h][d][t_pairsigma]
__device__ __half g_y[(size_t)BB * TT * EE];        // pair-sigma'd E
__device__ __half g_xt[(size_t)BB * TT * EE];       // x, pair-sigma'd E
__device__ __half g_wqkvT[(size_t)3 * EE * EE];     // W_qkv^T K-major, pair-sigma'd K
__device__ __half g_wprojT[(size_t)EE * EE];        // W_proj^T K-major, pair-sigma'd K

__device__ __forceinline__ uint32_t f2h2(float lo, float hi) {
    uint32_t r;
    asm("cvt.rn.f16x2.f32 %0, %1, %2;" : "=r"(r) : "f"(hi), "f"(lo));
    return r;
}

__device__ __forceinline__ void mma_fp16(float c[4], uint32_t a0, uint32_t a1,
                                         uint32_t a2, uint32_t a3,
                                         uint32_t b0, uint32_t b1) {
    asm volatile(
        "mma.sync.aligned.m16n8k16.row.col.f32.f16.f16.f32 "
        "{%0,%1,%2,%3}, {%4,%5,%6,%7}, {%8,%9}, {%0,%1,%2,%3};"
        : "+f"(c[0]), "+f"(c[1]), "+f"(c[2]), "+f"(c[3])
        : "r"(a0), "r"(a1), "r"(a2), "r"(a3), "r"(b0), "r"(b1));
}

__device__ __forceinline__ void cp16h(__half* dst_smem, const __half* src) {
    uint32_t d = (uint32_t)__cvta_generic_to_shared(dst_smem);
    asm volatile("cp.async.cg.shared.global [%0], [%1], 16;"
                 :: "r"(d), "l"(src) : "memory");
}
#define CP_COMMIT() asm volatile("cp.async.commit_group;" ::: "memory")
#define CP_WAIT1()  asm volatile("cp.async.wait_group 1;" ::: "memory")

// ---------------------------------------------------------------------------
// Fused prep: [0,2048) cvt x -> xt (fp16, pair-sigma);
//             [2048,5120) transpose Wqkv; [5120,6144) transpose Wproj.
// ---------------------------------------------------------------------------
__device__ __forceinline__ void do_transpose_h(
    const float* __restrict__ in, __half* __restrict__ out,
    int R, int C, int bx, int by, int tid, float (*t)[33])
{
    const int tx = tid & 31, ty = tid >> 5;   // 32 x 8
    const int x = bx * 32 + tx;
    const int y = by * 32 + ty;
#pragma unroll
    for (int j = 0; j < 32; j += 8)
        t[ty + j][tx] = in[(size_t)(y + j) * C + x];
    __syncthreads();
    const int nl = tid >> 3;          // out row 0..31
    const int pc = tid & 7;           // pair col 0..7
    const int orow = bx * 32 + nl;
#pragma unroll
    for (int pi = 0; pi < 2; ++pi) {
        const int p = pc + (pi << 3);           // 0..15
        const int g = p >> 3, j = p & 7;
        const int sig = ((j & 3) << 1) | (j >> 2);
        const int kpos = by * 32 + (g << 4) + (sig << 1);
        const uint32_t h2 = f2h2(t[2 * p][nl], t[2 * p + 1][nl]);
        *(uint32_t*)(out + (size_t)orow * R + kpos) = h2;
    }
}

__global__ __launch_bounds__(256) void prep_kernel(
    const float* __restrict__ x, __half* __restrict__ xt,
    const float* __restrict__ Wqkv, __half* __restrict__ wqkvT,
    const float* __restrict__ Wproj, __half* __restrict__ wprojT)
{
    __shared__ float t[32][33];
    const int bid = blockIdx.x;
    const int tid = threadIdx.x;
    if (bid < 2048) {
        const size_t i = ((size_t)bid * 256 + tid) * 16;
        float f[16];
        *(float4*)(f + 0)  = *(const float4*)(x + i);
        *(float4*)(f + 4)  = *(const float4*)(x + i + 4);
        *(float4*)(f + 8)  = *(const float4*)(x + i + 8);
        *(float4*)(f + 12) = *(const float4*)(x + i + 12);
        uint32_t u[8];
#pragma unroll
        for (int j = 0; j < 8; ++j)
            u[((j & 3) << 1) | (j >> 2)] = f2h2(f[2 * j], f[2 * j + 1]);
        *(uint4*)(xt + i)     = make_uint4(u[0], u[1], u[2], u[3]);
        *(uint4*)(xt + i + 8) = make_uint4(u[4], u[5], u[6], u[7]);
    } else if (bid < 2048 + 3072) {
        const int idx = bid - 2048;
        do_transpose_h(Wqkv, wqkvT, EE, 3 * EE, idx % 96, idx / 96, tid, t);
    } else {
        const int idx = bid - 2048 - 3072;
        do_transpose_h(Wproj, wprojT, EE, EE, idx % 32, idx / 32, tid, t);
    }
}

// ---------------------------------------------------------------------------
// fp16 m16n8k16 GEMM, pair-sigma operands, cp.async double buffer.
// CTA tile 128(M) x 256(N), 8 warps of 64x64 (wm 0..1, wn 0..3), 1 CTA/SM.
// BK = 64. MODE 0: fp32 output. MODE 1: fp16 output; Q cols scaled 1/8 +
// pair-sigma'd; K cols pair-sigma'd; V cols transposed to Vt.
// ---------------------------------------------------------------------------
#define SMH 80                       // smem row stride (fp16)
#define A_TILE_H (128 * SMH)
#define B_TILE_H (256 * SMH)
#define GEMM_SMEM_BYTES ((2 * A_TILE_H + 2 * B_TILE_H) * 2)

template <int MODE>
__global__ __launch_bounds__(256, 1) void gemm_mma_fp16(
    const __half* __restrict__ A, const __half* __restrict__ Bt,
    const float* __restrict__ bias, float* __restrict__ Cf,
    __half* __restrict__ Ch, __half* __restrict__ Vt,
    int M, int N, int K)
{
    extern __shared__ __half smh[];
    __half* As = smh;                  // [2][128][SMH]
    __half* Bs = smh + 2 * A_TILE_H;   // [2][256][SMH]

    const int tid  = threadIdx.x;
    const int wid  = tid >> 5;
    const int lane = tid & 31;
    const int wm   = wid >> 2;         // 0..1
    const int wn   = wid & 3;          // 0..3
    const int r1   = lane >> 2;
    const int cg   = lane & 3;
    const int m0   = blockIdx.y << 7;
    const int n0   = blockIdx.x << 8;

    const __half* Ap  = A  + (size_t)m0 * K;
    const __half* Btp = Bt + (size_t)n0 * K;

    const int lr  = tid >> 3;          // row base, +32 per iter
    const int lc8 = (tid & 7) << 3;    // fp16 col 0..56

    // Prologue: k-tile 0 -> buffer 0 (A: 128 rows, B: 256 rows)
#pragma unroll
    for (int i = 0; i < 4; ++i)
        cp16h(As + (lr + (i << 5)) * SMH + lc8,
              Ap + (size_t)(lr + (i << 5)) * K + lc8);
#pragma unroll
    for (int i = 0; i < 8; ++i)
        cp16h(Bs + (lr + (i << 5)) * SMH + lc8,
              Btp + (size_t)(lr + (i << 5)) * K + lc8);
    CP_COMMIT();

    float acc[4][8][4] = {};

    const int nT = K >> 6;
    for (int t = 0; t < nT; ++t) {
        const int buf = t & 1;
        if (t + 1 < nT) {
            const int k0 = (t + 1) << 6;
            const int nxt = (t + 1) & 1;
#pragma unroll
            for (int i = 0; i < 4; ++i)
                cp16h(As + nxt * A_TILE_H + (lr + (i << 5)) * SMH + lc8,
                      Ap + (size_t)(lr + (i << 5)) * K + k0 + lc8);
#pragma unroll
            for (int i = 0; i < 8; ++i)
                cp16h(Bs + nxt * B_TILE_H + (lr + (i << 5)) * SMH + lc8,
                      Btp + (size_t)(lr + (i << 5)) * K + k0 + lc8);
        }
        CP_COMMIT();
        CP_WAIT1();
        __syncthreads();

        const __half* Ab = As + buf * A_TILE_H;
        const __half* Bb = Bs + buf * B_TILE_H;
#pragma unroll
        for (int ks = 0; ks < 4; ++ks) {
            const int kk = (ks << 4) + (cg << 2);
            uint2 af[4][2];
#pragma unroll
            for (int mt = 0; mt < 4; ++mt) {
                const __half* p = Ab + (wm * 64 + mt * 16 + r1) * SMH + kk;
                af[mt][0] = *(const uint2*)(p);
                af[mt][1] = *(const uint2*)(p + 8 * SMH);
            }
#pragma unroll
            for (int nt = 0; nt < 8; ++nt) {
                const uint2 bf =
                    *(const uint2*)(Bb + (wn * 64 + nt * 8 + r1) * SMH + kk);
#pragma unroll
                for (int mt = 0; mt < 4; ++mt)
                    mma_fp16(acc[mt][nt], af[mt][0].x, af[mt][1].x,
                             af[mt][0].y, af[mt][1].y, bf.x, bf.y);
            }
        }
        __syncthreads();
    }

    // Epilogue
#pragma unroll
    for (int mt = 0; mt < 4; ++mt) {
#pragma unroll
        for (int nt = 0; nt < 8; ++nt) {
            const int row  = m0 + wm * 64 + mt * 16 + r1;
            const int colb = n0 + wn * 64 + nt * 8;
            const float2 bv = *(const float2*)(bias + colb + 2 * cg);
            float v0 = acc[mt][nt][0] + bv.x;
            float v1 = acc[mt][nt][1] + bv.y;
            float v2 = acc[mt][nt][2] + bv.x;
            float v3 = acc[mt][nt][3] + bv.y;
            if (MODE == 1) {
                if (colb < EE) { v0 *= 0.125f; v1 *= 0.125f; v2 *= 0.125f; v3 *= 0.125f; }
                if (colb < 2 * EE) {
                    // Q,K: pair-sigma'd positions within 16-col groups
                    const int pos = (colb & ~15) + 4 * cg + 2 * (nt & 1);
                    *(uint32_t*)(Ch + (size_t)row * N + pos)       = f2h2(v0, v1);
                    *(uint32_t*)(Ch + (size_t)(row + 8) * N + pos) = f2h2(v2, v3);
                } else {
                    // V -> Vt[b][h][d][t_pairsigma]; d natural, t pair-sigma
                    const int vb  = colb - 2 * EE;
                    const int hh  = vb >> 6;
                    const int dl  = (vb & 63) + 2 * cg;
                    const int bb2 = row >> 11;
                    const int trw = row & (TT - 1);
                    // t pair-sigma: sigma(m)=2m for m=r1>>1<4 within 16-group
                    const int tq = trw - r1 + 4 * (r1 >> 1) + (r1 & 1);
                    __half* vp = Vt + (size_t)(bb2 * HH + hh) * DD * TT;
                    vp[(size_t)dl * TT + tq]           = __float2half_rn(v0);
                    vp[(size_t)(dl + 1) * TT + tq]     = __float2half_rn(v1);
                    vp[(size_t)dl * TT + tq + 2]       = __float2half_rn(v2);
                    vp[(size_t)(dl + 1) * TT + tq + 2] = __float2half_rn(v3);
                }
            } else {
                *(float2*)(Cf + (size_t)row * N + colb + 2 * cg) =
                    make_float2(v0, v1);
                *(float2*)(Cf + (size_t)(row + 8) * N + colb + 2 * cg) =
                    make_float2(v2, v3);
            }
        }
    }
}

// ---------------------------------------------------------------------------
// fp16 tensor-core flash attention (causal), 128 q/CTA, 256 threads,
// 2 CTAs/SM, reversed qb order. Unchanged from round 14.
// ---------------------------------------------------------------------------
#define ASTH 80
#define PSTH 80
#define ATT_SMEM_BYTES ((2 * 128 * ASTH + 8 * 16 * PSTH) * 2)

__global__ __launch_bounds__(256, 2) void attn_mma(
    const __half* __restrict__ qkv, const __half* __restrict__ vt,
    __half* __restrict__ y)
{
    extern __shared__ __half smh[];
    __half* Pw = smh + 2 * 128 * ASTH;   // [8][16][PSTH]

    const int tid  = threadIdx.x;
    const int wid  = tid >> 5;
    const int lane = tid & 31;
    const int r1   = lane >> 2;
    const int cg   = lane & 3;
    const int q0   = (int)(gridDim.x - 1 - blockIdx.x) << 7;  // reversed
    const int h    = blockIdx.y;
    const int b    = blockIdx.z;
    const int qw   = q0 + (wid << 4);

    const size_t rs = (size_t)3 * EE;
    const __half* base = qkv + (size_t)(b * TT) * rs + h * DD;
    const __half* vtp  = vt + (size_t)(b * HH + h) * DD * TT;

    // ---- Stage Q (scaled, pair-sigma'd) into smh rows 0..127 ----
#pragma unroll
    for (int i = 0; i < 4; ++i) {
        const int idx = tid + (i << 8);
        const int row = idx >> 3;            // 0..127
        const int c8  = (idx & 7) << 3;
        *(uint4*)(smh + row * ASTH + c8) =
            *(const uint4*)(base + (size_t)(q0 + row) * rs + c8);
    }
    __syncthreads();

    uint32_t qf[4][4];
#pragma unroll
    for (int ks = 0; ks < 4; ++ks) {
        const __half* p = smh + ((wid << 4) + r1) * ASTH + (ks << 4) + (cg << 2);
        const uint2 lo = *(const uint2*)(p);
        const uint2 hi = *(const uint2*)(p + 8 * ASTH);
        qf[ks][0] = lo.x; qf[ks][1] = hi.x; qf[ks][2] = lo.y; qf[ks][3] = hi.y;
    }
    __syncthreads();

    const int nkb = (q0 >> 6) + 2;

    const int srow = tid >> 3;          // 0..31, +32 per iter
    const int sc8  = (tid & 7) << 3;

#pragma unroll
    for (int i = 0; i < 2; ++i) {
        const int row = srow + (i << 5);
        cp16h(smh + row * ASTH + sc8,        base + (size_t)row * rs + EE + sc8);
        cp16h(smh + (64 + row) * ASTH + sc8, vtp + (size_t)row * TT + sc8);
    }
    CP_COMMIT();

    float o[8][4] = {};
    float m0r = -INFINITY, m1r = -INFINITY;
    float l0r = 0.f, l1r = 0.f;

    for (int kb = 0; kb < nkb; ++kb) {
        const int buf = kb & 1;
        if (kb + 1 < nkb) {
            const int k0n = (kb + 1) << 6;
            __half* nb = smh + ((kb + 1) & 1) * 128 * ASTH;
#pragma unroll
            for (int i = 0; i < 2; ++i) {
                const int row = srow + (i << 5);
                cp16h(nb + row * ASTH + sc8,
                      base + (size_t)(k0n + row) * rs + EE + sc8);
                cp16h(nb + (64 + row) * ASTH + sc8,
                      vtp + (size_t)row * TT + k0n + sc8);
            }
        }
        CP_COMMIT();
        CP_WAIT1();
        __syncthreads();

        const int k0 = kb << 6;
        const __half* Ks  = smh + buf * 128 * ASTH;
        const __half* VTs = Ks + 64 * ASTH;

        if (k0 <= qw + 15) {
            // ---- S = Q @ K^T ----
            float s[8][4] = {};
#pragma unroll
            for (int ks = 0; ks < 4; ++ks) {
#pragma unroll
                for (int nt = 0; nt < 8; ++nt) {
                    const uint2 bp = *(const uint2*)(
                        Ks + ((nt << 3) + r1) * ASTH + (ks << 4) + (cg << 2));
                    mma_fp16(s[nt], qf[ks][0], qf[ks][1], qf[ks][2], qf[ks][3],
                             bp.x, bp.y);
                }
            }

            // ---- Causal mask ----
            if (k0 + 63 > qw) {
                const int row0 = qw + r1, row1 = row0 + 8;
#pragma unroll
                for (int nt = 0; nt < 8; ++nt) {
                    const int col = k0 + (nt << 3) + 2 * cg;
                    if (col > row0)     s[nt][0] = -1e30f;
                    if (col + 1 > row0) s[nt][1] = -1e30f;
                    if (col > row1)     s[nt][2] = -1e30f;
                    if (col + 1 > row1) s[nt][3] = -1e30f;
                }
            }

            // ---- Online softmax ----
            float mx0 = -INFINITY, mx1 = -INFINITY;
#pragma unroll
            for (int nt = 0; nt < 8; ++nt) {
                mx0 = fmaxf(mx0, fmaxf(s[nt][0], s[nt][1]));
                mx1 = fmaxf(mx1, fmaxf(s[nt][2], s[nt][3]));
            }
            mx0 = fmaxf(mx0, __shfl_xor_sync(0xffffffffu, mx0, 1));
            mx0 = fmaxf(mx0, __shfl_xor_sync(0xffffffffu, mx0, 2));
            mx1 = fmaxf(mx1, __shfl_xor_sync(0xffffffffu, mx1, 1));
            mx1 = fmaxf(mx1, __shfl_xor_sync(0xffffffffu, mx1, 2));

            const float mn0 = fmaxf(m0r, mx0);
            const float mn1 = fmaxf(m1r, mx1);
            const float c0 = __expf(m0r - mn0);
            const float c1 = __expf(m1r - mn1);
            m0r = mn0; m1r = mn1;

            float sum0 = 0.f, sum1 = 0.f;
#pragma unroll
            for (int nt = 0; nt < 8; ++nt) {
                s[nt][0] = __expf(s[nt][0] - mn0);
                s[nt][1] = __expf(s[nt][1] - mn0);
                s[nt][2] = __expf(s[nt][2] - mn1);
                s[nt][3] = __expf(s[nt][3] - mn1);
                sum0 += s[nt][0] + s[nt][1];
                sum1 += s[nt][2] + s[nt][3];
            }
            sum0 += __shfl_xor_sync(0xffffffffu, sum0, 1);
            sum0 += __shfl_xor_sync(0xffffffffu, sum0, 2);
            sum1 += __shfl_xor_sync(0xffffffffu, sum1, 1);
            sum1 += __shfl_xor_sync(0xffffffffu, sum1, 2);
            l0r = l0r * c0 + sum0;
            l1r = l1r * c1 + sum1;

#pragma unroll
            for (int nt = 0; nt < 8; ++nt) {
                o[nt][0] *= c0; o[nt][1] *= c0;
                o[nt][2] *= c1; o[nt][3] *= c1;
            }

            // ---- P -> per-warp smem strip (fp16, key pair-sigma) ----
            __half* pw = Pw + wid * 16 * PSTH;
#pragma unroll
            for (int nt = 0; nt < 8; ++nt) {
                const int pos = ((nt & ~1) << 3) + 4 * cg + 2 * (nt & 1);
                *(uint32_t*)(pw + r1 * PSTH + pos)       = f2h2(s[nt][0], s[nt][1]);
                *(uint32_t*)(pw + (r1 + 8) * PSTH + pos) = f2h2(s[nt][2], s[nt][3]);
            }
            __syncwarp();

            // ---- O += P @ V (all frags LDS.64) ----
#pragma unroll
            for (int ks = 0; ks < 4; ++ks) {
                const __half* pa = pw + r1 * PSTH + (ks << 4) + (cg << 2);
                const uint2 lo = *(const uint2*)(pa);
                const uint2 hi = *(const uint2*)(pa + 8 * PSTH);
#pragma unroll
                for (int nt = 0; nt < 8; ++nt) {
                    const uint2 bp = *(const uint2*)(
                        VTs + ((nt << 3) + r1) * ASTH + (ks << 4) + (cg << 2));
                    mma_fp16(o[nt], lo.x, hi.x, lo.y, hi.y, bp.x, bp.y);
                }
            }
            __syncwarp();
        }
        __syncthreads();
    }

    // ---- Normalize + write y (fp16, pair-sigma along E for proj GEMM) ----
    const float inv0 = 1.0f / l0r;
    const float inv1 = 1.0f / l1r;
    const size_t row0 = (size_t)(b * TT + qw + r1);
#pragma unroll
    for (int nt = 0; nt < 8; ++nt) {
        const int pos = h * DD + ((nt & ~1) << 3) + 4 * cg + 2 * (nt & 1);
        *(uint32_t*)(y + row0 * EE + pos) =
            f2h2(o[nt][0] * inv0, o[nt][1] * inv0);
        *(uint32_t*)(y + (row0 + 8) * EE + pos) =
            f2h2(o[nt][2] * inv1, o[nt][3] * inv1);
    }
}

// ---------------------------------------------------------------------------
// Launch (single stream, full-size grids)
// ---------------------------------------------------------------------------
extern "C" void kernel_launch(void* const* d_in, const int* in_sizes, int n_in,
                              void* d_out, int out_size)
{
    const float* x     = (const float*)d_in[0];
    const float* Wqkv  = (const float*)d_in[1];
    const float* bqkv  = (const float*)d_in[2];
    const float* Wproj = (const float*)d_in[3];
    const float* bproj = (const float*)d_in[4];
    float* out = (float*)d_out;

    __half *qkv, *vt, *y, *xt, *wqkvT, *wprojT;
    cudaGetSymbolAddress((void**)&qkv, g_qkv);
    cudaGetSymbolAddress((void**)&vt, g_vt);
    cudaGetSymbolAddress((void**)&y, g_y);
    cudaGetSymbolAddress((void**)&xt, g_xt);
    cudaGetSymbolAddress((void**)&wqkvT, g_wqkvT);
    cudaGetSymbolAddress((void**)&wprojT, g_wprojT);

    cudaFuncSetAttribute(gemm_mma_fp16<0>,
                         cudaFuncAttributeMaxDynamicSharedMemorySize, GEMM_SMEM_BYTES);
    cudaFuncSetAttribute(gemm_mma_fp16<1>,
                         cudaFuncAttributeMaxDynamicSharedMemorySize, GEMM_SMEM_BYTES);
    cudaFuncSetAttribute(attn_mma,
                         cudaFuncAttributeMaxDynamicSharedMemorySize, ATT_SMEM_BYTES);

    const int M = BB * TT;

    // 0) Fused prep: x -> fp16 pair-sigma; W^T -> fp16 K-major pair-sigma
    prep_kernel<<<6144, 256>>>(x, xt, Wqkv, wqkvT, Wproj, wprojT);

    // 1) QKV projection -> qkv (Q scaled+sigma, K sigma) + Vt (transposed)
    gemm_mma_fp16<1><<<dim3(3 * EE / 256, M / 128), 256, GEMM_SMEM_BYTES>>>(
        xt, wqkvT, bqkv, nullptr, qkv, vt, M, 3 * EE, EE);

    // 2) Causal flash attention -> fp16 y
    attn_mma<<<dim3(TT / 128, HH, BB), 256, ATT_SMEM_BYTES>>>(qkv, vt, y);

    // 3) Output projection -> fp32 out
    gemm_mma_fp16<0><<<dim3(EE / 256, M / 128), 256, GEMM_SMEM_BYTES>>>(
        y, wprojT, bproj, out, nullptr, nullptr, M, EE, EE);
}

// round 16
// speedup vs baseline: 1.2307x; 1.2307x over previous
#include <cuda_runtime.h>
#include <cuda_fp16.h>
#include <math.h>
#include <stdint.h>

// Problem dims (fixed by reference)
#define BB 4
#define TT 2048
#define EE 1024
#define HH 16
#define DD 64

// fp16 operand buffers use pair-sigma interleaved k-groups of 16:
//   pair j (elements 2j,2j+1) of a 16-group stored at pair-position
//   sigma(j) = ((j&3)<<1) | (j>>2).
// Then an m16n8k16 fragment's k-slots for thread cg are 4 contiguous fp16
// at offset 4*cg: pairs cg (k=2cg,2cg+1) and cg+4 (k=2cg+8,2cg+9).

__device__ __half g_qkv[(size_t)BB * TT * 3 * EE];  // Q/K pair-sigma'd d, Q pre-scaled
__device__ __half g_vt[(size_t)BB * HH * DD * TT];  // V^T: [b][h][d][t_pairsigma]
__device__ __half g_y[(size_t)BB * TT * EE];        // pair-sigma'd E
__device__ __half g_xt[(size_t)BB * TT * EE];       // x, pair-sigma'd E
__device__ __half g_wqkvT[(size_t)3 * EE * EE];     // W_qkv^T K-major, pair-sigma'd K
__device__ __half g_wprojT[(size_t)EE * EE];        // W_proj^T K-major, pair-sigma'd K

__device__ __forceinline__ uint32_t f2h2(float lo, float hi) {
    uint32_t r;
    asm("cvt.rn.f16x2.f32 %0, %1, %2;" : "=r"(r) : "f"(hi), "f"(lo));
    return r;
}

__device__ __forceinline__ void mma_fp16(float c[4], uint32_t a0, uint32_t a1,
                                         uint32_t a2, uint32_t a3,
                                         uint32_t b0, uint32_t b1) {
    asm volatile(
        "mma.sync.aligned.m16n8k16.row.col.f32.f16.f16.f32 "
        "{%0,%1,%2,%3}, {%4,%5,%6,%7}, {%8,%9}, {%0,%1,%2,%3};"
        : "+f"(c[0]), "+f"(c[1]), "+f"(c[2]), "+f"(c[3])
        : "r"(a0), "r"(a1), "r"(a2), "r"(a3), "r"(b0), "r"(b1));
}

__device__ __forceinline__ void cp16h(__half* dst_smem, const __half* src) {
    uint32_t d = (uint32_t)__cvta_generic_to_shared(dst_smem);
    asm volatile("cp.async.cg.shared.global [%0], [%1], 16;"
                 :: "r"(d), "l"(src) : "memory");
}
#define CP_COMMIT() asm volatile("cp.async.commit_group;" ::: "memory")
#define CP_WAIT1()  asm volatile("cp.async.wait_group 1;" ::: "memory")

// ---------------------------------------------------------------------------
// Fused prep: [0,2048) cvt x -> xt (fp16, pair-sigma);
//             [2048,5120) transpose Wqkv; [5120,6144) transpose Wproj.
// ---------------------------------------------------------------------------
__device__ __forceinline__ void do_transpose_h(
    const float* __restrict__ in, __half* __restrict__ out,
    int R, int C, int bx, int by, int tid, float (*t)[33])
{
    const int tx = tid & 31, ty = tid >> 5;   // 32 x 8
    const int x = bx * 32 + tx;
    const int y = by * 32 + ty;
#pragma unroll
    for (int j = 0; j < 32; j += 8)
        t[ty + j][tx] = in[(size_t)(y + j) * C + x];
    __syncthreads();
    const int nl = tid >> 3;          // out row 0..31
    const int pc = tid & 7;           // pair col 0..7
    const int orow = bx * 32 + nl;
#pragma unroll
    for (int pi = 0; pi < 2; ++pi) {
        const int p = pc + (pi << 3);           // 0..15
        const int g = p >> 3, j = p & 7;
        const int sig = ((j & 3) << 1) | (j >> 2);
        const int kpos = by * 32 + (g << 4) + (sig << 1);
        const uint32_t h2 = f2h2(t[2 * p][nl], t[2 * p + 1][nl]);
        *(uint32_t*)(out + (size_t)orow * R + kpos) = h2;
    }
}

__global__ __launch_bounds__(256) void prep_kernel(
    const float* __restrict__ x, __half* __restrict__ xt,
    const float* __restrict__ Wqkv, __half* __restrict__ wqkvT,
    const float* __restrict__ Wproj, __half* __restrict__ wprojT)
{
    __shared__ float t[32][33];
    const int bid = blockIdx.x;
    const int tid = threadIdx.x;
    if (bid < 2048) {
        const size_t i = ((size_t)bid * 256 + tid) * 16;
        float f[16];
        *(float4*)(f + 0)  = *(const float4*)(x + i);
        *(float4*)(f + 4)  = *(const float4*)(x + i + 4);
        *(float4*)(f + 8)  = *(const float4*)(x + i + 8);
        *(float4*)(f + 12) = *(const float4*)(x + i + 12);
        uint32_t u[8];
#pragma unroll
        for (int j = 0; j < 8; ++j)
            u[((j & 3) << 1) | (j >> 2)] = f2h2(f[2 * j], f[2 * j + 1]);
        *(uint4*)(xt + i)     = make_uint4(u[0], u[1], u[2], u[3]);
        *(uint4*)(xt + i + 8) = make_uint4(u[4], u[5], u[6], u[7]);
    } else if (bid < 2048 + 3072) {
        const int idx = bid - 2048;
        do_transpose_h(Wqkv, wqkvT, EE, 3 * EE, idx % 96, idx / 96, tid, t);
    } else {
        const int idx = bid - 2048 - 3072;
        do_transpose_h(Wproj, wprojT, EE, EE, idx % 32, idx / 32, tid, t);
    }
}

// ---------------------------------------------------------------------------
// fp16 m16n8k16 GEMM (round-14 config: 128x128 CTA tile, warp 64x32,
// 2 CTAs/SM), pair-sigma operands, cp.async double buffer. BK = 64.
// MODE 0: fp32 output. MODE 1: fp16 output; Q cols scaled 1/8 + pair-sigma'd;
// K cols pair-sigma'd; V cols transposed to Vt.
// ---------------------------------------------------------------------------
#define SMH 80                       // smem row stride (fp16)
#define TILE_H (128 * SMH)
#define GEMM_SMEM_BYTES (2 * 2 * TILE_H * 2)

template <int MODE>
__global__ __launch_bounds__(256, 2) void gemm_mma_fp16(
    const __half* __restrict__ A, const __half* __restrict__ Bt,
    const float* __restrict__ bias, float* __restrict__ Cf,
    __half* __restrict__ Ch, __half* __restrict__ Vt,
    int M, int N, int K)
{
    extern __shared__ __half smh[];
    __half* As = smh;                 // [2][128][SMH]
    __half* Bs = smh + 2 * TILE_H;    // [2][128][SMH]

    const int tid  = threadIdx.x;
    const int wid  = tid >> 5;
    const int lane = tid & 31;
    const int wm   = wid >> 2;
    const int wn   = wid & 3;
    const int r1   = lane >> 2;
    const int cg   = lane & 3;
    const int m0   = blockIdx.y << 7;
    const int n0   = blockIdx.x << 7;

    const __half* Ap  = A  + (size_t)m0 * K;
    const __half* Btp = Bt + (size_t)n0 * K;

    const int lr  = tid >> 3;          // row base, +32 per iter
    const int lc8 = (tid & 7) << 3;    // fp16 col 0..56

    // Prologue: k-tile 0 -> buffer 0 (64 fp16 per row = 8 chunks)
#pragma unroll
    for (int i = 0; i < 4; ++i) {
        const int r = lr + (i << 5);
        cp16h(As + r * SMH + lc8, Ap + (size_t)r * K + lc8);
        cp16h(Bs + r * SMH + lc8, Btp + (size_t)r * K + lc8);
    }
    CP_COMMIT();

    float acc[4][4][4] = {};

    const int nT = K >> 6;
    for (int t = 0; t < nT; ++t) {
        const int buf = t & 1;
        if (t + 1 < nT) {
            const int k0 = (t + 1) << 6;
            const int nxt = (t + 1) & 1;
#pragma unroll
            for (int i = 0; i < 4; ++i) {
                const int r = lr + (i << 5);
                cp16h(As + nxt * TILE_H + r * SMH + lc8,
                      Ap + (size_t)r * K + k0 + lc8);
                cp16h(Bs + nxt * TILE_H + r * SMH + lc8,
                      Btp + (size_t)r * K + k0 + lc8);
            }
        }
        CP_COMMIT();
        CP_WAIT1();
        __syncthreads();

        const __half* Ab = As + buf * TILE_H;
        const __half* Bb = Bs + buf * TILE_H;
#pragma unroll
        for (int ks = 0; ks < 4; ++ks) {
            const int kk = (ks << 4) + (cg << 2);
            uint2 bf[4];
#pragma unroll
            for (int nt = 0; nt < 4; ++nt)
                bf[nt] = *(const uint2*)(Bb + (wn * 32 + nt * 8 + r1) * SMH + kk);
#pragma unroll
            for (int mt = 0; mt < 4; ++mt) {
                const __half* p = Ab + (wm * 64 + mt * 16 + r1) * SMH + kk;
                const uint2 lo = *(const uint2*)(p);
                const uint2 hi = *(const uint2*)(p + 8 * SMH);
#pragma unroll
                for (int nt = 0; nt < 4; ++nt)
                    mma_fp16(acc[mt][nt], lo.x, hi.x, lo.y, hi.y,
                             bf[nt].x, bf[nt].y);
            }
        }
        __syncthreads();
    }

    // Epilogue
#pragma unroll
    for (int mt = 0; mt < 4; ++mt) {
#pragma unroll
        for (int nt = 0; nt < 4; ++nt) {
            const int row  = m0 + wm * 64 + mt * 16 + r1;
            const int colb = n0 + wn * 32 + nt * 8;
            const float2 bv = *(const float2*)(bias + colb + 2 * cg);
            float v0 = acc[mt][nt][0] + bv.x;
            float v1 = acc[mt][nt][1] + bv.y;
            float v2 = acc[mt][nt][2] + bv.x;
            float v3 = acc[mt][nt][3] + bv.y;
            if (MODE == 1) {
                if (colb < EE) { v0 *= 0.125f; v1 *= 0.125f; v2 *= 0.125f; v3 *= 0.125f; }
                if (colb < 2 * EE) {
                    // Q,K: pair-sigma'd positions within 16-col groups
                    const int pos = (colb & ~15) + 4 * cg + 2 * (nt & 1);
                    *(uint32_t*)(Ch + (size_t)row * N + pos)       = f2h2(v0, v1);
                    *(uint32_t*)(Ch + (size_t)(row + 8) * N + pos) = f2h2(v2, v3);
                } else {
                    // V -> Vt[b][h][d][t_pairsigma]; d natural, t pair-sigma
                    const int vb  = colb - 2 * EE;
                    const int hh  = vb >> 6;
                    const int dl  = (vb & 63) + 2 * cg;
                    const int bb2 = row >> 11;
                    const int trw = row & (TT - 1);
                    const int tq = trw - r1 + 4 * (r1 >> 1) + (r1 & 1);
                    __half* vp = Vt + (size_t)(bb2 * HH + hh) * DD * TT;
                    vp[(size_t)dl * TT + tq]           = __float2half_rn(v0);
                    vp[(size_t)(dl + 1) * TT + tq]     = __float2half_rn(v1);
                    vp[(size_t)dl * TT + tq + 2]       = __float2half_rn(v2);
                    vp[(size_t)(dl + 1) * TT + tq + 2] = __float2half_rn(v3);
                }
            } else {
                *(float2*)(Cf + (size_t)row * N + colb + 2 * cg) =
                    make_float2(v0, v1);
                *(float2*)(Cf + (size_t)(row + 8) * N + colb + 2 * cg) =
                    make_float2(v2, v3);
            }
        }
    }
}

// ---------------------------------------------------------------------------
// fp16 tensor-core flash attention (causal), 128 q/CTA, 256 threads,
// 2 CTAs/SM, reversed qb order. S C-frag reused DIRECTLY as PV A-frag
// (no P smem round trip): a0/a1 from s[2ks], a2/a3 from s[2ks+1].
// ---------------------------------------------------------------------------
#define ASTH 80
#define ATT_SMEM_BYTES ((2 * 128 * ASTH) * 2)

__global__ __launch_bounds__(256, 2) void attn_mma(
    const __half* __restrict__ qkv, const __half* __restrict__ vt,
    __half* __restrict__ y)
{
    extern __shared__ __half smh[];

    const int tid  = threadIdx.x;
    const int wid  = tid >> 5;
    const int lane = tid & 31;
    const int r1   = lane >> 2;
    const int cg   = lane & 3;
    const int q0   = (int)(gridDim.x - 1 - blockIdx.x) << 7;  // reversed
    const int h    = blockIdx.y;
    const int b    = blockIdx.z;
    const int qw   = q0 + (wid << 4);

    const size_t rs = (size_t)3 * EE;
    const __half* base = qkv + (size_t)(b * TT) * rs + h * DD;
    const __half* vtp  = vt + (size_t)(b * HH + h) * DD * TT;

    // ---- Stage Q (scaled, pair-sigma'd) into smh rows 0..127 ----
#pragma unroll
    for (int i = 0; i < 4; ++i) {
        const int idx = tid + (i << 8);
        const int row = idx >> 3;            // 0..127
        const int c8  = (idx & 7) << 3;
        *(uint4*)(smh + row * ASTH + c8) =
            *(const uint4*)(base + (size_t)(q0 + row) * rs + c8);
    }
    __syncthreads();

    uint32_t qf[4][4];
#pragma unroll
    for (int ks = 0; ks < 4; ++ks) {
        const __half* p = smh + ((wid << 4) + r1) * ASTH + (ks << 4) + (cg << 2);
        const uint2 lo = *(const uint2*)(p);
        const uint2 hi = *(const uint2*)(p + 8 * ASTH);
        qf[ks][0] = lo.x; qf[ks][1] = hi.x; qf[ks][2] = lo.y; qf[ks][3] = hi.y;
    }
    __syncthreads();

    const int nkb = (q0 >> 6) + 2;

    const int srow = tid >> 3;          // 0..31, +32 per iter
    const int sc8  = (tid & 7) << 3;

#pragma unroll
    for (int i = 0; i < 2; ++i) {
        const int row = srow + (i << 5);
        cp16h(smh + row * ASTH + sc8,        base + (size_t)row * rs + EE + sc8);
        cp16h(smh + (64 + row) * ASTH + sc8, vtp + (size_t)row * TT + sc8);
    }
    CP_COMMIT();

    float o[8][4] = {};
    float m0r = -INFINITY, m1r = -INFINITY;
    float l0r = 0.f, l1r = 0.f;

    for (int kb = 0; kb < nkb; ++kb) {
        const int buf = kb & 1;
        if (kb + 1 < nkb) {
            const int k0n = (kb + 1) << 6;
            __half* nb = smh + ((kb + 1) & 1) * 128 * ASTH;
#pragma unroll
            for (int i = 0; i < 2; ++i) {
                const int row = srow + (i << 5);
                cp16h(nb + row * ASTH + sc8,
                      base + (size_t)(k0n + row) * rs + EE + sc8);
                cp16h(nb + (64 + row) * ASTH + sc8,
                      vtp + (size_t)row * TT + k0n + sc8);
            }
        }
        CP_COMMIT();
        CP_WAIT1();
        __syncthreads();

        const int k0 = kb << 6;
        const __half* Ks  = smh + buf * 128 * ASTH;
        const __half* VTs = Ks + 64 * ASTH;

        if (k0 <= qw + 15) {
            // ---- S = Q @ K^T ----
            float s[8][4] = {};
#pragma unroll
            for (int ks = 0; ks < 4; ++ks) {
#pragma unroll
                for (int nt = 0; nt < 8; ++nt) {
                    const uint2 bp = *(const uint2*)(
                        Ks + ((nt << 3) + r1) * ASTH + (ks << 4) + (cg << 2));
                    mma_fp16(s[nt], qf[ks][0], qf[ks][1], qf[ks][2], qf[ks][3],
                             bp.x, bp.y);
                }
            }

            // ---- Causal mask ----
            if (k0 + 63 > qw) {
                const int row0 = qw + r1, row1 = row0 + 8;
#pragma unroll
                for (int nt = 0; nt < 8; ++nt) {
                    const int col = k0 + (nt << 3) + 2 * cg;
                    if (col > row0)     s[nt][0] = -1e30f;
                    if (col + 1 > row0) s[nt][1] = -1e30f;
                    if (col > row1)     s[nt][2] = -1e30f;
                    if (col + 1 > row1) s[nt][3] = -1e30f;
                }
            }

            // ---- Online softmax ----
            float mx0 = -INFINITY, mx1 = -INFINITY;
#pragma unroll
            for (int nt = 0; nt < 8; ++nt) {
                mx0 = fmaxf(mx0, fmaxf(s[nt][0], s[nt][1]));
                mx1 = fmaxf(mx1, fmaxf(s[nt][2], s[nt][3]));
            }
            mx0 = fmaxf(mx0, __shfl_xor_sync(0xffffffffu, mx0, 1));
            mx0 = fmaxf(mx0, __shfl_xor_sync(0xffffffffu, mx0, 2));
            mx1 = fmaxf(mx1, __shfl_xor_sync(0xffffffffu, mx1, 1));
            mx1 = fmaxf(mx1, __shfl_xor_sync(0xffffffffu, mx1, 2));

            const float mn0 = fmaxf(m0r, mx0);
            const float mn1 = fmaxf(m1r, mx1);
            const float c0 = __expf(m0r - mn0);
            const float c1 = __expf(m1r - mn1);
            m0r = mn0; m1r = mn1;

            float sum0 = 0.f, sum1 = 0.f;
#pragma unroll
            for (int nt = 0; nt < 8; ++nt) {
                s[nt][0] = __expf(s[nt][0] - mn0);
                s[nt][1] = __expf(s[nt][1] - mn0);
                s[nt][2] = __expf(s[nt][2] - mn1);
                s[nt][3] = __expf(s[nt][3] - mn1);
                sum0 += s[nt][0] + s[nt][1];
                sum1 += s[nt][2] + s[nt][3];
            }
            sum0 += __shfl_xor_sync(0xffffffffu, sum0, 1);
            sum0 += __shfl_xor_sync(0xffffffffu, sum0, 2);
            sum1 += __shfl_xor_sync(0xffffffffu, sum1, 1);
            sum1 += __shfl_xor_sync(0xffffffffu, sum1, 2);
            l0r = l0r * c0 + sum0;
            l1r = l1r * c1 + sum1;

#pragma unroll
            for (int nt = 0; nt < 8; ++nt) {
                o[nt][0] *= c0; o[nt][1] *= c0;
                o[nt][2] *= c1; o[nt][3] *= c1;
            }

            // ---- O += P @ V : S C-frag IS the PV A-frag (no smem round trip)
#pragma unroll
            for (int ks = 0; ks < 4; ++ks) {
                const uint32_t a0 = f2h2(s[2 * ks][0],     s[2 * ks][1]);
                const uint32_t a1 = f2h2(s[2 * ks][2],     s[2 * ks][3]);
                const uint32_t a2 = f2h2(s[2 * ks + 1][0], s[2 * ks + 1][1]);
                const uint32_t a3 = f2h2(s[2 * ks + 1][2], s[2 * ks + 1][3]);
#pragma unroll
                for (int nt = 0; nt < 8; ++nt) {
                    const uint2 bp = *(const uint2*)(
                        VTs + ((nt << 3) + r1) * ASTH + (ks << 4) + (cg << 2));
                    mma_fp16(o[nt], a0, a1, a2, a3, bp.x, bp.y);
                }
            }
        }
        __syncthreads();
    }

    // ---- Normalize + write y (fp16, pair-sigma along E for proj GEMM) ----
    const float inv0 = 1.0f / l0r;
    const float inv1 = 1.0f / l1r;
    const size_t row0 = (size_t)(b * TT + qw + r1);
#pragma unroll
    for (int nt = 0; nt < 8; ++nt) {
        const int pos = h * DD + ((nt & ~1) << 3) + 4 * cg + 2 * (nt & 1);
        *(uint32_t*)(y + row0 * EE + pos) =
            f2h2(o[nt][0] * inv0, o[nt][1] * inv0);
        *(uint32_t*)(y + (row0 + 8) * EE + pos) =
            f2h2(o[nt][2] * inv1, o[nt][3] * inv1);
    }
}

// ---------------------------------------------------------------------------
// Launch (single stream, full-size grids)
// ---------------------------------------------------------------------------
extern "C" void kernel_launch(void* const* d_in, const int* in_sizes, int n_in,
                              void* d_out, int out_size)
{
    const float* x     = (const float*)d_in[0];
    const float* Wqkv  = (const float*)d_in[1];
    const float* bqkv  = (const float*)d_in[2];
    const float* Wproj = (const float*)d_in[3];
    const float* bproj = (const float*)d_in[4];
    float* out = (float*)d_out;

    __half *qkv, *vt, *y, *xt, *wqkvT, *wprojT;
    cudaGetSymbolAddress((void**)&qkv, g_qkv);
    cudaGetSymbolAddress((void**)&vt, g_vt);
    cudaGetSymbolAddress((void**)&y, g_y);
    cudaGetSymbolAddress((void**)&xt, g_xt);
    cudaGetSymbolAddress((void**)&wqkvT, g_wqkvT);
    cudaGetSymbolAddress((void**)&wprojT, g_wprojT);

    cudaFuncSetAttribute(gemm_mma_fp16<0>,
                         cudaFuncAttributeMaxDynamicSharedMemorySize, GEMM_SMEM_BYTES);
    cudaFuncSetAttribute(gemm_mma_fp16<1>,
                         cudaFuncAttributeMaxDynamicSharedMemorySize, GEMM_SMEM_BYTES);
    cudaFuncSetAttribute(attn_mma,
                         cudaFuncAttributeMaxDynamicSharedMemorySize, ATT_SMEM_BYTES);

    const int M = BB * TT;

    // 0) Fused prep: x -> fp16 pair-sigma; W^T -> fp16 K-major pair-sigma
    prep_kernel<<<6144, 256>>>(x, xt, Wqkv, wqkvT, Wproj, wprojT);

    // 1) QKV projection -> qkv (Q scaled+sigma, K sigma) + Vt (transposed)
    gemm_mma_fp16<1><<<dim3(3 * EE / 128, M / 128), 256, GEMM_SMEM_BYTES>>>(
        xt, wqkvT, bqkv, nullptr, qkv, vt, M, 3 * EE, EE);

    // 2) Causal flash attention -> fp16 y
    attn_mma<<<dim3(TT / 128, HH, BB), 256, ATT_SMEM_BYTES>>>(qkv, vt, y);

    // 3) Output projection -> fp32 out
    gemm_mma_fp16<0><<<dim3(EE / 128, M / 128), 256, GEMM_SMEM_BYTES>>>(
        y, wprojT, bproj, out, nullptr, nullptr, M, EE, EE);
}

// round 17
// speedup vs baseline: 1.2937x; 1.0513x over previous
#include <cuda_runtime.h>
#include <cuda_fp16.h>
#include <math.h>
#include <stdint.h>

// Problem dims (fixed by reference)
#define BB 4
#define TT 2048
#define EE 1024
#define HH 16
#define DD 64

// fp16 operand buffers use pair-sigma interleaved k-groups of 16 (global):
//   pair j (elements 2j,2j+1) stored at pair-position sigma(j)=((j&3)<<1)|(j>>2)
// so an m16n8k16 fragment's k-slots for thread cg are 4 contiguous fp16.
// SMEM tiles additionally use a chunk-rotation swizzle: 16B chunk c of row r
// is stored at chunk ((c + 2*(r&3)) & 7) — conflict-free for both cp.async
// stores and LDS.64 fragment reads, with zero padding (row = 64 fp16).

__device__ __half g_qkv[(size_t)BB * TT * 3 * EE];  // Q/K pair-sigma'd d, Q pre-scaled
__device__ __half g_vt[(size_t)BB * HH * DD * TT];  // V^T: [b][h][d][t_pairsigma]
__device__ __half g_y[(size_t)BB * TT * EE];        // pair-sigma'd E
__device__ __half g_xt[(size_t)BB * TT * EE];       // x, pair-sigma'd E
__device__ __half g_wqkvT[(size_t)3 * EE * EE];     // W_qkv^T K-major, pair-sigma'd K
__device__ __half g_wprojT[(size_t)EE * EE];        // W_proj^T K-major, pair-sigma'd K

__device__ __forceinline__ uint32_t f2h2(float lo, float hi) {
    uint32_t r;
    asm("cvt.rn.f16x2.f32 %0, %1, %2;" : "=r"(r) : "f"(hi), "f"(lo));
    return r;
}

__device__ __forceinline__ void mma_fp16(float c[4], uint32_t a0, uint32_t a1,
                                         uint32_t a2, uint32_t a3,
                                         uint32_t b0, uint32_t b1) {
    asm volatile(
        "mma.sync.aligned.m16n8k16.row.col.f32.f16.f16.f32 "
        "{%0,%1,%2,%3}, {%4,%5,%6,%7}, {%8,%9}, {%0,%1,%2,%3};"
        : "+f"(c[0]), "+f"(c[1]), "+f"(c[2]), "+f"(c[3])
        : "r"(a0), "r"(a1), "r"(a2), "r"(a3), "r"(b0), "r"(b1));
}

__device__ __forceinline__ void cp16h(__half* dst_smem, const __half* src) {
    uint32_t d = (uint32_t)__cvta_generic_to_shared(dst_smem);
    asm volatile("cp.async.cg.shared.global [%0], [%1], 16;"
                 :: "r"(d), "l"(src) : "memory");
}
#define CP_COMMIT() asm volatile("cp.async.commit_group;" ::: "memory")
#define CP_WAIT1()  asm volatile("cp.async.wait_group 1;" ::: "memory")

// ---------------------------------------------------------------------------
// Fused prep: [0,2048) cvt x -> xt (fp16, pair-sigma);
//             [2048,5120) transpose Wqkv; [5120,6144) transpose Wproj.
// (unchanged from round 16)
// ---------------------------------------------------------------------------
__device__ __forceinline__ void do_transpose_h(
    const float* __restrict__ in, __half* __restrict__ out,
    int R, int C, int bx, int by, int tid, float (*t)[33])
{
    const int tx = tid & 31, ty = tid >> 5;   // 32 x 8
    const int x = bx * 32 + tx;
    const int y = by * 32 + ty;
#pragma unroll
    for (int j = 0; j < 32; j += 8)
        t[ty + j][tx] = in[(size_t)(y + j) * C + x];
    __syncthreads();
    const int nl = tid >> 3;          // out row 0..31
    const int pc = tid & 7;           // pair col 0..7
    const int orow = bx * 32 + nl;
#pragma unroll
    for (int pi = 0; pi < 2; ++pi) {
        const int p = pc + (pi << 3);           // 0..15
        const int g = p >> 3, j = p & 7;
        const int sig = ((j & 3) << 1) | (j >> 2);
        const int kpos = by * 32 + (g << 4) + (sig << 1);
        const uint32_t h2 = f2h2(t[2 * p][nl], t[2 * p + 1][nl]);
        *(uint32_t*)(out + (size_t)orow * R + kpos) = h2;
    }
}

__global__ __launch_bounds__(256) void prep_kernel(
    const float* __restrict__ x, __half* __restrict__ xt,
    const float* __restrict__ Wqkv, __half* __restrict__ wqkvT,
    const float* __restrict__ Wproj, __half* __restrict__ wprojT)
{
    __shared__ float t[32][33];
    const int bid = blockIdx.x;
    const int tid = threadIdx.x;
    if (bid < 2048) {
        const size_t i = ((size_t)bid * 256 + tid) * 16;
        float f[16];
        *(float4*)(f + 0)  = *(const float4*)(x + i);
        *(float4*)(f + 4)  = *(const float4*)(x + i + 4);
        *(float4*)(f + 8)  = *(const float4*)(x + i + 8);
        *(float4*)(f + 12) = *(const float4*)(x + i + 12);
        uint32_t u[8];
#pragma unroll
        for (int j = 0; j < 8; ++j)
            u[((j & 3) << 1) | (j >> 2)] = f2h2(f[2 * j], f[2 * j + 1]);
        *(uint4*)(xt + i)     = make_uint4(u[0], u[1], u[2], u[3]);
        *(uint4*)(xt + i + 8) = make_uint4(u[4], u[5], u[6], u[7]);
    } else if (bid < 2048 + 3072) {
        const int idx = bid - 2048;
        do_transpose_h(Wqkv, wqkvT, EE, 3 * EE, idx % 96, idx / 96, tid, t);
    } else {
        const int idx = bid - 2048 - 3072;
        do_transpose_h(Wproj, wprojT, EE, EE, idx % 32, idx / 32, tid, t);
    }
}

// ---------------------------------------------------------------------------
// fp16 m16n8k16 GEMM: 128x128 CTA tile, warp 64x32, 2 CTAs/SM, BK=64.
// 3-stage cp.async pipeline, ONE barrier per k-tile, chunk-rotation smem
// swizzle (stride 64, no padding).
// MODE 0: fp32 output. MODE 1: fp16 output; Q cols scaled 1/8 + pair-sigma'd;
// K cols pair-sigma'd; V cols transposed to Vt.
// ---------------------------------------------------------------------------
#define TILE_H (128 * 64)
#define GEMM_SMEM_BYTES (3 * 2 * TILE_H * 2)   // 98304

template <int MODE>
__global__ __launch_bounds__(256, 2) void gemm_mma_fp16(
    const __half* __restrict__ A, const __half* __restrict__ Bt,
    const float* __restrict__ bias, float* __restrict__ Cf,
    __half* __restrict__ Ch, __half* __restrict__ Vt,
    int M, int N, int K)
{
    extern __shared__ __half smh[];
    __half* As = smh;                 // [3][128][64]
    __half* Bs = smh + 3 * TILE_H;    // [3][128][64]

    const int tid  = threadIdx.x;
    const int wid  = tid >> 5;
    const int lane = tid & 31;
    const int wm   = wid >> 2;
    const int wn   = wid & 3;
    const int r1   = lane >> 2;
    const int cg   = lane & 3;
    const int m0   = blockIdx.y << 7;
    const int n0   = blockIdx.x << 7;

    const __half* Ap  = A  + (size_t)m0 * K;
    const __half* Btp = Bt + (size_t)n0 * K;

    const int lr    = tid >> 3;                       // row base, +32/iter
    const int lc8   = (tid & 7) << 3;                 // src fp16 col
    const int dstc8 = ((((tid & 7) + 2 * ((tid >> 3) & 3)) & 7) << 3); // swz dst

    // Prologue: k-tile 0 -> stage 0
#pragma unroll
    for (int i = 0; i < 4; ++i) {
        const int r = lr + (i << 5);
        cp16h(As + r * 64 + dstc8, Ap + (size_t)r * K + lc8);
        cp16h(Bs + r * 64 + dstc8, Btp + (size_t)r * K + lc8);
    }
    CP_COMMIT();

    float acc[4][4][4] = {};

    const int rot = 2 * (r1 & 3);
    const int nT = K >> 6;
    int stage = 0;
    for (int t = 0; t < nT; ++t) {
        if (t + 1 < nT) {
            const int k0 = (t + 1) << 6;
            const int ns = (t + 1) % 3;
#pragma unroll
            for (int i = 0; i < 4; ++i) {
                const int r = lr + (i << 5);
                cp16h(As + ns * TILE_H + r * 64 + dstc8,
                      Ap + (size_t)r * K + k0 + lc8);
                cp16h(Bs + ns * TILE_H + r * 64 + dstc8,
                      Btp + (size_t)r * K + k0 + lc8);
            }
        }
        CP_COMMIT();
        CP_WAIT1();
        __syncthreads();

        const __half* Ab = As + stage * TILE_H;
        const __half* Bb = Bs + stage * TILE_H;
#pragma unroll
        for (int ks = 0; ks < 4; ++ks) {
            const int kf = (((2 * ks + (cg >> 1) + rot) & 7) << 3) + ((cg & 1) << 2);
            uint2 bf[4];
#pragma unroll
            for (int nt = 0; nt < 4; ++nt)
                bf[nt] = *(const uint2*)(Bb + (wn * 32 + nt * 8 + r1) * 64 + kf);
#pragma unroll
            for (int mt = 0; mt < 4; ++mt) {
                const __half* p = Ab + (wm * 64 + mt * 16 + r1) * 64 + kf;
                const uint2 lo = *(const uint2*)(p);
                const uint2 hi = *(const uint2*)(p + 8 * 64);
#pragma unroll
                for (int nt = 0; nt < 4; ++nt)
                    mma_fp16(acc[mt][nt], lo.x, hi.x, lo.y, hi.y,
                             bf[nt].x, bf[nt].y);
            }
        }
        stage = (stage + 1 == 3) ? 0 : stage + 1;
    }

    // Epilogue (unchanged)
#pragma unroll
    for (int mt = 0; mt < 4; ++mt) {
#pragma unroll
        for (int nt = 0; nt < 4; ++nt) {
            const int row  = m0 + wm * 64 + mt * 16 + r1;
            const int colb = n0 + wn * 32 + nt * 8;
            const float2 bv = *(const float2*)(bias + colb + 2 * cg);
            float v0 = acc[mt][nt][0] + bv.x;
            float v1 = acc[mt][nt][1] + bv.y;
            float v2 = acc[mt][nt][2] + bv.x;
            float v3 = acc[mt][nt][3] + bv.y;
            if (MODE == 1) {
                if (colb < EE) { v0 *= 0.125f; v1 *= 0.125f; v2 *= 0.125f; v3 *= 0.125f; }
                if (colb < 2 * EE) {
                    const int pos = (colb & ~15) + 4 * cg + 2 * (nt & 1);
                    *(uint32_t*)(Ch + (size_t)row * N + pos)       = f2h2(v0, v1);
                    *(uint32_t*)(Ch + (size_t)(row + 8) * N + pos) = f2h2(v2, v3);
                } else {
                    const int vb  = colb - 2 * EE;
                    const int hh  = vb >> 6;
                    const int dl  = (vb & 63) + 2 * cg;
                    const int bb2 = row >> 11;
                    const int trw = row & (TT - 1);
                    const int tq = trw - r1 + 4 * (r1 >> 1) + (r1 & 1);
                    __half* vp = Vt + (size_t)(bb2 * HH + hh) * DD * TT;
                    vp[(size_t)dl * TT + tq]           = __float2half_rn(v0);
                    vp[(size_t)(dl + 1) * TT + tq]     = __float2half_rn(v1);
                    vp[(size_t)dl * TT + tq + 2]       = __float2half_rn(v2);
                    vp[(size_t)(dl + 1) * TT + tq + 2] = __float2half_rn(v3);
                }
            } else {
                *(float2*)(Cf + (size_t)row * N + colb + 2 * cg) =
                    make_float2(v0, v1);
                *(float2*)(Cf + (size_t)(row + 8) * N + colb + 2 * cg) =
                    make_float2(v2, v3);
            }
        }
    }
}

// ---------------------------------------------------------------------------
// fp16 tensor-core flash attention (causal), 128 q/CTA, 256 threads,
// 2 CTAs/SM, reversed qb order. 3-stage single-barrier pipeline, swizzled
// smem, S C-frag reused directly as PV A-frag.
// ---------------------------------------------------------------------------
#define ATILE_H (128 * 64)
#define ATT_SMEM_BYTES (3 * ATILE_H * 2)   // 49152

__global__ __launch_bounds__(256, 2) void attn_mma(
    const __half* __restrict__ qkv, const __half* __restrict__ vt,
    __half* __restrict__ y)
{
    extern __shared__ __half smh[];

    const int tid  = threadIdx.x;
    const int wid  = tid >> 5;
    const int lane = tid & 31;
    const int r1   = lane >> 2;
    const int cg   = lane & 3;
    const int q0   = (int)(gridDim.x - 1 - blockIdx.x) << 7;  // reversed
    const int h    = blockIdx.y;
    const int b    = blockIdx.z;
    const int qw   = q0 + (wid << 4);

    const size_t rs = (size_t)3 * EE;
    const __half* base = qkv + (size_t)(b * TT) * rs + h * DD;
    const __half* vtp  = vt + (size_t)(b * HH + h) * DD * TT;

    const int dstc8 = ((((tid & 7) + 2 * ((tid >> 3) & 3)) & 7) << 3);
    const int rot   = 2 * (r1 & 3);

    // ---- Stage Q (scaled, pair-sigma'd) into rows 0..127 (swizzled) ----
#pragma unroll
    for (int i = 0; i < 4; ++i) {
        const int idx = tid + (i << 8);
        const int row = idx >> 3;            // 0..127
        const int c8  = (idx & 7) << 3;
        *(uint4*)(smh + row * 64 + dstc8) =
            *(const uint4*)(base + (size_t)(q0 + row) * rs + c8);
    }
    __syncthreads();

    uint32_t qf[4][4];
#pragma unroll
    for (int ks = 0; ks < 4; ++ks) {
        const int kf = (((2 * ks + (cg >> 1) + rot) & 7) << 3) + ((cg & 1) << 2);
        const __half* p = smh + ((wid << 4) + r1) * 64 + kf;
        const uint2 lo = *(const uint2*)(p);
        const uint2 hi = *(const uint2*)(p + 8 * 64);
        qf[ks][0] = lo.x; qf[ks][1] = hi.x; qf[ks][2] = lo.y; qf[ks][3] = hi.y;
    }
    __syncthreads();

    const int nkb = (q0 >> 6) + 2;

    const int srow = tid >> 3;          // 0..31, +32 per iter
    const int sc8  = (tid & 7) << 3;

    // Prologue: tile 0 -> stage 0 (K rows 0-63, VT rows 64-127)
#pragma unroll
    for (int i = 0; i < 2; ++i) {
        const int row = srow + (i << 5);
        cp16h(smh + row * 64 + dstc8,        base + (size_t)row * rs + EE + sc8);
        cp16h(smh + (64 + row) * 64 + dstc8, vtp + (size_t)row * TT + sc8);
    }
    CP_COMMIT();

    float o[8][4] = {};
    float m0r = -INFINITY, m1r = -INFINITY;
    float l0r = 0.f, l1r = 0.f;

    int stage = 0;
    for (int kb = 0; kb < nkb; ++kb) {
        if (kb + 1 < nkb) {
            const int k0n = (kb + 1) << 6;
            __half* nb = smh + ((kb + 1) % 3) * ATILE_H;
#pragma unroll
            for (int i = 0; i < 2; ++i) {
                const int row = srow + (i << 5);
                cp16h(nb + row * 64 + dstc8,
                      base + (size_t)(k0n + row) * rs + EE + sc8);
                cp16h(nb + (64 + row) * 64 + dstc8,
                      vtp + (size_t)row * TT + k0n + sc8);
            }
        }
        CP_COMMIT();
        CP_WAIT1();
        __syncthreads();

        const int k0 = kb << 6;
        const __half* Ks  = smh + stage * ATILE_H;
        const __half* VTs = Ks + 64 * 64;

        if (k0 <= qw + 15) {
            // ---- S = Q @ K^T ----
            float s[8][4] = {};
#pragma unroll
            for (int ks = 0; ks < 4; ++ks) {
                const int kf = (((2 * ks + (cg >> 1) + rot) & 7) << 3) + ((cg & 1) << 2);
#pragma unroll
                for (int nt = 0; nt < 8; ++nt) {
                    const uint2 bp = *(const uint2*)(
                        Ks + ((nt << 3) + r1) * 64 + kf);
                    mma_fp16(s[nt], qf[ks][0], qf[ks][1], qf[ks][2], qf[ks][3],
                             bp.x, bp.y);
                }
            }

            // ---- Causal mask ----
            if (k0 + 63 > qw) {
                const int row0 = qw + r1, row1 = row0 + 8;
#pragma unroll
                for (int nt = 0; nt < 8; ++nt) {
                    const int col = k0 + (nt << 3) + 2 * cg;
                    if (col > row0)     s[nt][0] = -1e30f;
                    if (col + 1 > row0) s[nt][1] = -1e30f;
                    if (col > row1)     s[nt][2] = -1e30f;
                    if (col + 1 > row1) s[nt][3] = -1e30f;
                }
            }

            // ---- Online softmax ----
            float mx0 = -INFINITY, mx1 = -INFINITY;
#pragma unroll
            for (int nt = 0; nt < 8; ++nt) {
                mx0 = fmaxf(mx0, fmaxf(s[nt][0], s[nt][1]));
                mx1 = fmaxf(mx1, fmaxf(s[nt][2], s[nt][3]));
            }
            mx0 = fmaxf(mx0, __shfl_xor_sync(0xffffffffu, mx0, 1));
            mx0 = fmaxf(mx0, __shfl_xor_sync(0xffffffffu, mx0, 2));
            mx1 = fmaxf(mx1, __shfl_xor_sync(0xffffffffu, mx1, 1));
            mx1 = fmaxf(mx1, __shfl_xor_sync(0xffffffffu, mx1, 2));

            const float mn0 = fmaxf(m0r, mx0);
            const float mn1 = fmaxf(m1r, mx1);
            const float c0 = __expf(m0r - mn0);
            const float c1 = __expf(m1r - mn1);
            m0r = mn0; m1r = mn1;

            float sum0 = 0.f, sum1 = 0.f;
#pragma unroll
            for (int nt = 0; nt < 8; ++nt) {
                s[nt][0] = __expf(s[nt][0] - mn0);
                s[nt][1] = __expf(s[nt][1] - mn0);
                s[nt][2] = __expf(s[nt][2] - mn1);
                s[nt][3] = __expf(s[nt][3] - mn1);
                sum0 += s[nt][0] + s[nt][1];
                sum1 += s[nt][2] + s[nt][3];
            }
            sum0 += __shfl_xor_sync(0xffffffffu, sum0, 1);
            sum0 += __shfl_xor_sync(0xffffffffu, sum0, 2);
            sum1 += __shfl_xor_sync(0xffffffffu, sum1, 1);
            sum1 += __shfl_xor_sync(0xffffffffu, sum1, 2);
            l0r = l0r * c0 + sum0;
            l1r = l1r * c1 + sum1;

#pragma unroll
            for (int nt = 0; nt < 8; ++nt) {
                o[nt][0] *= c0; o[nt][1] *= c0;
                o[nt][2] *= c1; o[nt][3] *= c1;
            }

            // ---- O += P @ V : S C-frag IS the PV A-frag ----
#pragma unroll
            for (int ks = 0; ks < 4; ++ks) {
                const uint32_t a0 = f2h2(s[2 * ks][0],     s[2 * ks][1]);
                const uint32_t a1 = f2h2(s[2 * ks][2],     s[2 * ks][3]);
                const uint32_t a2 = f2h2(s[2 * ks + 1][0], s[2 * ks + 1][1]);
                const uint32_t a3 = f2h2(s[2 * ks + 1][2], s[2 * ks + 1][3]);
                const int kf = (((2 * ks + (cg >> 1) + rot) & 7) << 3) + ((cg & 1) << 2);
#pragma unroll
                for (int nt = 0; nt < 8; ++nt) {
                    const uint2 bp = *(const uint2*)(
                        VTs + ((nt << 3) + r1) * 64 + kf);
                    mma_fp16(o[nt], a0, a1, a2, a3, bp.x, bp.y);
                }
            }
        }
        stage = (stage + 1 == 3) ? 0 : stage + 1;
    }

    // ---- Normalize + write y (fp16, pair-sigma along E for proj GEMM) ----
    const float inv0 = 1.0f / l0r;
    const float inv1 = 1.0f / l1r;
    const size_t row0 = (size_t)(b * TT + qw + r1);
#pragma unroll
    for (int nt = 0; nt < 8; ++nt) {
        const int pos = h * DD + ((nt & ~1) << 3) + 4 * cg + 2 * (nt & 1);
        *(uint32_t*)(y + row0 * EE + pos) =
            f2h2(o[nt][0] * inv0, o[nt][1] * inv0);
        *(uint32_t*)(y + (row0 + 8) * EE + pos) =
            f2h2(o[nt][2] * inv1, o[nt][3] * inv1);
    }
}

// ---------------------------------------------------------------------------
// Launch (single stream, full-size grids)
// ---------------------------------------------------------------------------
extern "C" void kernel_launch(void* const* d_in, const int* in_sizes, int n_in,
                              void* d_out, int out_size)
{
    const float* x     = (const float*)d_in[0];
    const float* Wqkv  = (const float*)d_in[1];
    const float* bqkv  = (const float*)d_in[2];
    const float* Wproj = (const float*)d_in[3];
    const float* bproj = (const float*)d_in[4];
    float* out = (float*)d_out;

    __half *qkv, *vt, *y, *xt, *wqkvT, *wprojT;
    cudaGetSymbolAddress((void**)&qkv, g_qkv);
    cudaGetSymbolAddress((void**)&vt, g_vt);
    cudaGetSymbolAddress((void**)&y, g_y);
    cudaGetSymbolAddress((void**)&xt, g_xt);
    cudaGetSymbolAddress((void**)&wqkvT, g_wqkvT);
    cudaGetSymbolAddress((void**)&wprojT, g_wprojT);

    cudaFuncSetAttribute(gemm_mma_fp16<0>,
                         cudaFuncAttributeMaxDynamicSharedMemorySize, GEMM_SMEM_BYTES);
    cudaFuncSetAttribute(gemm_mma_fp16<1>,
                         cudaFuncAttributeMaxDynamicSharedMemorySize, GEMM_SMEM_BYTES);
    cudaFuncSetAttribute(attn_mma,
                         cudaFuncAttributeMaxDynamicSharedMemorySize, ATT_SMEM_BYTES);

    const int M = BB * TT;

    // 0) Fused prep: x -> fp16 pair-sigma; W^T -> fp16 K-major pair-sigma
    prep_kernel<<<6144, 256>>>(x, xt, Wqkv, wqkvT, Wproj, wprojT);

    // 1) QKV projection -> qkv (Q scaled+sigma, K sigma) + Vt (transposed)
    gemm_mma_fp16<1><<<dim3(3 * EE / 128, M / 128), 256, GEMM_SMEM_BYTES>>>(
        xt, wqkvT, bqkv, nullptr, qkv, vt, M, 3 * EE, EE);

    // 2) Causal flash attention -> fp16 y
    attn_mma<<<dim3(TT / 128, HH, BB), 256, ATT_SMEM_BYTES>>>(qkv, vt, y);

    // 3) Output projection -> fp32 out
    gemm_mma_fp16<0><<<dim3(EE / 128, M / 128), 256, GEMM_SMEM_BYTES>>>(
        y, wprojT, bproj, out, nullptr, nullptr, M, EE, EE);
}